// round 12
// baseline (speedup 1.0000x reference)
#include <cuda_runtime.h>
#include <cstdint>

#define Bn 64
#define Tn 2048
#define Dn 512
#define Un 32
#define FULLM 0xffffffffu
typedef unsigned long long ull;

// ---------------- packed f32x2 ops ----------------
__device__ __forceinline__ ull fma2(ull a, ull b, ull c) {
    ull d;
    asm("fma.rn.f32x2 %0, %1, %2, %3;" : "=l"(d) : "l"(a), "l"(b), "l"(c));
    return d;
}
__device__ __forceinline__ void unpack2(ull a, float& lo, float& hi) {
    asm("mov.b64 {%0, %1}, %2;" : "=f"(lo), "=f"(hi) : "l"(a));
}
__device__ __forceinline__ ull pack2(float lo, float hi) {
    ull d;
    asm("mov.b64 %0, {%1, %2};" : "=l"(d) : "f"(lo), "f"(hi));
    return d;
}
__device__ __forceinline__ void cp16(float* smem_ptr, const float* gptr) {
    unsigned saddr = (unsigned)__cvta_generic_to_shared(smem_ptr);
    asm volatile("cp.async.cg.shared.global [%0], [%1], 16;" :: "r"(saddr), "l"(gptr));
}

#define NCHUNK 32
#define NJOBS (NCHUNK * Bn)  // 2048 gemm chunk-jobs
#define NBLOCKS 456          // 152 SMs x occ3

// viterbi smem layout (byte offsets)
#define PBUF 65536           // 2 par x 4 p x 144B (32 floats, padded)  -> 1152
#define SVAL 66688           // 2 par x 32 j x 16B (4 prevals)          -> 1024
#define SIDX 67712           // 2 par x 128 bytes                        -> 256
#define PMAP 67968           // 32 chunks x 32 origins                   -> 1024
#define ANCH 68992           // 32 ints                                  -> 128
#define SFIN 69120           // 8
#define SMEM_BYTES 69136

// scratch: 16 MB logits + control block (flags | roles | counters), one memset
__device__ float g_logits[(size_t)Bn * Tn * Un];
// [0,2048) chunk flags (b*32+c); [2048,2304) sm role; [2304] vit ctr; [2305] job ctr
__device__ int g_ctrl[2048 + 256 + 2];

// ================= GEMM job: 64 rows (one 64-step chunk of one batch) ==========
__device__ void gemm_role(int c, int b, const float* __restrict__ x,
                          const float* __restrict__ W,
                          const float* __restrict__ bias, char* smem) {
    float* sx = (float*)smem;  // 2 x 64 x 128 floats (64KB)
    const int tid = threadIdx.x;
    const size_t row0 = (size_t)b * Tn + c * 64;

    {
        const float* gsrc = x + row0 * Dn;
#pragma unroll
        for (int q = 0; q < 16; q++) {
            int lin = tid + 128 * q;
            int rr = lin >> 5, cc = lin & 31;
            cp16(sx + rr * 128 + cc * 4, gsrc + (size_t)rr * Dn + cc * 4);
        }
        asm volatile("cp.async.commit_group;");
    }

    const int w = tid >> 5, u = tid & 31;
    const int wr0 = w * 16;

    ull acc[16];
#pragma unroll
    for (int r = 0; r < 16; r++) acc[r] = 0ull;

    for (int kt = 0; kt < 4; kt++) {
        if (kt < 3) {
            const float* gsrc = x + row0 * Dn + (kt + 1) * 128;
            float* sdst = sx + ((kt + 1) & 1) * 8192;
#pragma unroll
            for (int q = 0; q < 16; q++) {
                int lin = tid + 128 * q;
                int rr = lin >> 5, cc = lin & 31;
                cp16(sdst + rr * 128 + cc * 4, gsrc + (size_t)rr * Dn + cc * 4);
            }
            asm volatile("cp.async.commit_group;");
            asm volatile("cp.async.wait_group 1;");
        } else {
            asm volatile("cp.async.wait_group 0;");
        }
        __syncthreads();

        const float* xbuf = sx + (kt & 1) * 8192;
        const float* wg = W + (kt * 128) * Un + u;
        for (int k8 = 0; k8 < 128; k8 += 8) {
            float wv0 = __ldg(wg + (k8 + 0) * Un);
            float wv1 = __ldg(wg + (k8 + 1) * Un);
            float wv2 = __ldg(wg + (k8 + 2) * Un);
            float wv3 = __ldg(wg + (k8 + 3) * Un);
            float wv4 = __ldg(wg + (k8 + 4) * Un);
            float wv5 = __ldg(wg + (k8 + 5) * Un);
            float wv6 = __ldg(wg + (k8 + 6) * Un);
            float wv7 = __ldg(wg + (k8 + 7) * Un);
            ull wp0 = pack2(wv0, wv1), wp1 = pack2(wv2, wv3);
            ull wp2 = pack2(wv4, wv5), wp3 = pack2(wv6, wv7);
#pragma unroll
            for (int r = 0; r < 16; r++) {
                const float* xr = xbuf + (wr0 + r) * 128 + k8;
                ulonglong2 x0 = *(const ulonglong2*)(xr);
                ulonglong2 x1 = *(const ulonglong2*)(xr + 4);
                acc[r] = fma2(x0.x, wp0, acc[r]);
                acc[r] = fma2(x0.y, wp1, acc[r]);
                acc[r] = fma2(x1.x, wp2, acc[r]);
                acc[r] = fma2(x1.y, wp3, acc[r]);
            }
        }
        __syncthreads();
    }

    float bu = bias[u];
#pragma unroll
    for (int r = 0; r < 16; r++) {
        float lo, hi;
        unpack2(acc[r], lo, hi);
        g_logits[(row0 + wr0 + r) * Un + u] = lo + hi + bu;
    }
    __syncthreads();
    if (tid == 0) {
        __threadfence();
        atomicExch(&g_ctrl[b * NCHUNK + c], 1);
    }
}

// ================= Viterbi: deferred cross-sub reduction ======================
// tid: j = tid>>2 (target tag), sub = tid&3 (i-range sub*8..sub*8+7)
__device__ __forceinline__ float ldclamp(const float* lg, int t, int tmax, int j) {
    int ti = t <= tmax ? t : tmax;
    return lg[ti * Un + j];
}

__device__ __forceinline__ void vstep(int t, float lgt, const float* tc, char* sm8,
                                      unsigned char* bp, int j, int sub) {
    __syncthreads();  // prior step's partial stores visible
    const int par = (t - 1) & 1;
    const char* pb = sm8 + PBUF + par * 576;
    const int qoff = sub * 32;  // byte offset of my first i-quad in a p-row
    // load 4 partials x 8 i's (conflict-free: 4 distinct quads per p across subs)
    float4 q0a = *(const float4*)(pb + 0 * 144 + qoff);
    float4 q0b = *(const float4*)(pb + 0 * 144 + qoff + 16);
    float4 q1a = *(const float4*)(pb + 1 * 144 + qoff);
    float4 q1b = *(const float4*)(pb + 1 * 144 + qoff + 16);
    float4 q2a = *(const float4*)(pb + 2 * 144 + qoff);
    float4 q2b = *(const float4*)(pb + 2 * 144 + qoff + 16);
    float4 q3a = *(const float4*)(pb + 3 * 144 + qoff);
    float4 q3b = *(const float4*)(pb + 3 * 144 + qoff + 16);
    // alpha[i] = max_p partial[p][i] (includes prior logit; exact by monotonicity)
    float a0 = fmaxf(fmaxf(q0a.x, q1a.x), fmaxf(q2a.x, q3a.x));
    float a1 = fmaxf(fmaxf(q0a.y, q1a.y), fmaxf(q2a.y, q3a.y));
    float a2 = fmaxf(fmaxf(q0a.z, q1a.z), fmaxf(q2a.z, q3a.z));
    float a3 = fmaxf(fmaxf(q0a.w, q1a.w), fmaxf(q2a.w, q3a.w));
    float a4 = fmaxf(fmaxf(q0b.x, q1b.x), fmaxf(q2b.x, q3b.x));
    float a5 = fmaxf(fmaxf(q0b.y, q1b.y), fmaxf(q2b.y, q3b.y));
    float a6 = fmaxf(fmaxf(q0b.z, q1b.z), fmaxf(q2b.z, q3b.z));
    float a7 = fmaxf(fmaxf(q0b.w, q1b.w), fmaxf(q2b.w, q3b.w));
    float v0 = a0 + tc[0], v1 = a1 + tc[1], v2 = a2 + tc[2], v3 = a3 + tc[3];
    float v4 = a4 + tc[4], v5 = a5 + tc[5], v6 = a6 + tc[6], v7 = a7 + tc[7];
    // 8 -> 1, strict '>' so lower index wins ties (matches jnp.argmax)
    bool g0 = v1 > v0; float m0 = fmaxf(v0, v1); int i0 = g0 ? 1 : 0;
    bool g1 = v3 > v2; float m1 = fmaxf(v2, v3); int i1 = g1 ? 3 : 2;
    bool g2 = v5 > v4; float m2 = fmaxf(v4, v5); int i2 = g2 ? 5 : 4;
    bool g3 = v7 > v6; float m3 = fmaxf(v6, v7); int i3 = g3 ? 7 : 6;
    bool h0 = m1 > m0; float n0 = fmaxf(m0, m1); int k0 = h0 ? i1 : i0;
    bool h1 = m3 > m2; float n1 = fmaxf(m2, m3); int k1 = h1 ? i3 : i2;
    bool hf = n1 > n0; float preval = fmaxf(n0, n1); int idx = sub * 8 + (hf ? k1 : k0);
    // resolve bp[t-1] from last step's (preval,idx) partials — off the alpha chain.
    // prevals exclude the logit: matches reference argmax-before-logit exactly.
    if (sub == 0) {
        float4 pv = *(const float4*)(sm8 + SVAL + par * 512 + j * 16);
        unsigned iw = *(const unsigned*)(sm8 + SIDX + par * 128 + j * 4);
        float bv = pv.x; unsigned bx = iw & 255u;
        if (pv.y > bv) { bv = pv.y; bx = (iw >> 8) & 255u; }
        if (pv.z > bv) { bv = pv.z; bx = (iw >> 16) & 255u; }
        if (pv.w > bv) { bv = pv.w; bx = (iw >> 24) & 255u; }
        bp[(t - 1) * 32 + j] = (unsigned char)bx;
    }
    // publish this step's partials (p = my sub, i = my j)
    const int cur = t & 1;
    *(float*)(sm8 + PBUF + cur * 576 + sub * 144 + j * 4) = preval + lgt;
    *(float*)(sm8 + SVAL + cur * 512 + j * 16 + sub * 4) = preval;
    *(unsigned char*)(sm8 + SIDX + cur * 128 + j * 4 + sub) = (unsigned char)idx;
}

__device__ __forceinline__ void waitchunk(int b, int c) {
    if (c > NCHUNK - 1) c = NCHUNK - 1;
    volatile int* f = &g_ctrl[b * NCHUNK + c];
    while (*f == 0) {}
    __threadfence();  // acquire
}

__device__ void viterbi_role(int b, const float* __restrict__ trans,
                             float* __restrict__ out, int write_pred, int write_score,
                             long long score_off, const int* __restrict__ nwords,
                             char* sm8) {
    unsigned char* bp = (unsigned char*)sm8;  // [0, 65536)
    unsigned char* pmap = (unsigned char*)(sm8 + PMAP);
    int* anch = (int*)(sm8 + ANCH);
    int* sfin = (int*)(sm8 + SFIN);

    const int tid = threadIdx.x;
    const int j = tid >> 2;
    const int sub = tid & 3;
    int len = nwords[b];
    if (len < 1) len = 1;
    if (len > Tn) len = Tn;
    const int tmax = len - 1;

    const float* lg = g_logits + (size_t)b * Tn * Un;

    float tc[8];
#pragma unroll
    for (int p = 0; p < 8; p++) tc[p] = trans[(sub * 8 + p) * Un + j];

    waitchunk(b, 0);
    // init partials: p=0 holds alpha0, p=1..3 = -inf
    if (tid < 32) {
        float a0 = lg[tid];
        *(float*)(sm8 + PBUF + 0 * 144 + tid * 4) = a0;
        *(float*)(sm8 + PBUF + 1 * 144 + tid * 4) = -3.0e38f;
        *(float*)(sm8 + PBUF + 2 * 144 + tid * 4) = -3.0e38f;
        *(float*)(sm8 + PBUF + 3 * 144 + tid * 4) = -3.0e38f;
    }
    __syncthreads();

    // 4-deep rotating logit prefetch
    float pl0 = ldclamp(lg, 1, tmax, j);
    float pl1 = ldclamp(lg, 2, tmax, j);
    float pl2 = ldclamp(lg, 3, tmax, j);
    float pl3 = ldclamp(lg, 4, tmax, j);

    int t = 1;
    for (; t + 3 <= tmax; t += 4) {
        if ((t & 63) == 1) waitchunk(b, (t >> 6) + 1);
        float n0 = ldclamp(lg, t + 4, tmax, j);
        float n1 = ldclamp(lg, t + 5, tmax, j);
        float n2 = ldclamp(lg, t + 6, tmax, j);
        float n3 = ldclamp(lg, t + 7, tmax, j);
        vstep(t, pl0, tc, sm8, bp, j, sub);
        vstep(t + 1, pl1, tc, sm8, bp, j, sub);
        vstep(t + 2, pl2, tc, sm8, bp, j, sub);
        vstep(t + 3, pl3, tc, sm8, bp, j, sub);
        pl0 = n0; pl1 = n1; pl2 = n2; pl3 = n3;
    }
    for (; t <= tmax; t++) {
        if ((t & 63) == 1) waitchunk(b, (t >> 6) + 1);
        vstep(t, pl0, tc, sm8, bp, j, sub);
        pl0 = pl1; pl1 = pl2; pl2 = pl3;
    }
    __syncthreads();

    // epilogue: final alpha + bp[tmax] resolution, then warp argmax
    const int fpar = tmax & 1;
    if (tid < 32) {
        const char* pb = sm8 + PBUF + fpar * 576;
        float x0 = *(const float*)(pb + 0 * 144 + tid * 4);
        float x1 = *(const float*)(pb + 1 * 144 + tid * 4);
        float x2 = *(const float*)(pb + 2 * 144 + tid * 4);
        float x3 = *(const float*)(pb + 3 * 144 + tid * 4);
        float av = fmaxf(fmaxf(x0, x1), fmaxf(x2, x3));
        if (tmax >= 1) {
            float4 pv = *(const float4*)(sm8 + SVAL + fpar * 512 + tid * 16);
            unsigned iw = *(const unsigned*)(sm8 + SIDX + fpar * 128 + tid * 4);
            float bv = pv.x; unsigned bx = iw & 255u;
            if (pv.y > bv) { bv = pv.y; bx = (iw >> 8) & 255u; }
            if (pv.z > bv) { bv = pv.z; bx = (iw >> 16) & 255u; }
            if (pv.w > bv) { bv = pv.w; bx = (iw >> 24) & 255u; }
            bp[tmax * 32 + tid] = (unsigned char)bx;
        }
        float bv2 = av;
        int bi = tid;
#pragma unroll
        for (int off = 16; off >= 1; off >>= 1) {
            float ov = __shfl_xor_sync(FULLM, bv2, off);
            int oi = __shfl_xor_sync(FULLM, bi, off);
            if (ov > bv2 || (ov == bv2 && oi < bi)) { bv2 = ov; bi = oi; }
        }
        if (tid == 0) {
            sfin[0] = bi;
            if (write_score) out[score_off + b] = bv2;
        }
    }
    __syncthreads();
    const int last_tag = sfin[0];

    if (write_pred) {
        // per-chunk backward maps: pmap[c][e] = tag@(c*64) given tag e@min((c+1)*64,tmax)
        int tg[8], clo[8], thi[8];
#pragma unroll
        for (int r = 0; r < 8; r++) {
            int p = tid + 128 * r;
            int c = p >> 5;
            tg[r] = p & 31;
            int th = (c + 1) << 6;
            if (th > tmax) th = tmax;
            clo[r] = c << 6;
            thi[r] = th;
        }
        for (int s = 0; s < 64; s++) {
#pragma unroll
            for (int r = 0; r < 8; r++) {
                int tt = thi[r] - s;
                if (tt > clo[r]) tg[r] = bp[tt * 32 + tg[r]];
            }
        }
#pragma unroll
        for (int r = 0; r < 8; r++) {
            int p = tid + 128 * r;
            pmap[(p >> 5) * 32 + (p & 31)] = (unsigned char)tg[r];
        }
        __syncthreads();

        const int cmax = tmax >> 6;
        if (tid == 0) {
            int a = last_tag;
            for (int c = cmax; c >= 0; --c) {
                a = pmap[c * 32 + a];
                anch[c] = a;  // tag @ c*64
            }
        }
        for (int tt = tmax + tid; tt < Tn; tt += 128)
            out[(size_t)b * Tn + tt] = (float)last_tag;
        __syncthreads();

        if (tid <= cmax) {
            int thi2 = (tid == cmax) ? tmax : ((tid + 1) << 6);
            int tg2 = (tid == cmax) ? last_tag : anch[tid + 1];
            for (int tt = thi2; tt > (tid << 6); --tt) {
                tg2 = bp[tt * 32 + tg2];
                out[(size_t)b * Tn + tt - 1] = (float)tg2;
            }
        }
    }
}

// ================= persistent fused kernel with SM-role isolation ==============
__global__ __launch_bounds__(128, 3) void crf_fused(const float* __restrict__ x,
                                                    const int* __restrict__ nwords,
                                                    const float* __restrict__ W,
                                                    const float* __restrict__ trans,
                                                    const float* __restrict__ bias,
                                                    float* __restrict__ out,
                                                    int write_pred, int write_score,
                                                    long long score_off) {
    extern __shared__ char smem[];
    __shared__ int s_role;
    __shared__ int s_batch;
    __shared__ int s_job;

    const int tid = threadIdx.x;
    if (tid == 0) {
        unsigned smid;
        asm("mov.u32 %0, %%smid;" : "=r"(smid));
        int* rp = &g_ctrl[2048 + (smid & 255)];
        int r = atomicCAS(rp, 0, 1);
        if (r == 0) {
            int vb = atomicAdd(&g_ctrl[2304], 1);
            if (vb < Bn) {
                s_batch = vb;
                atomicExch(rp, 3);
                s_role = 1;
            } else {
                atomicExch(rp, 2);
                s_role = 2;
            }
        } else {
            volatile int* vp = rp;
            int v;
            while ((v = *vp) < 2) {}
            s_role = (v == 3) ? 0 : 2;
        }
    }
    __syncthreads();
    const int role = s_role;
    if (role == 0) return;

    if (role == 1) {
        viterbi_role(s_batch, trans, out, write_pred, write_score, score_off,
                     nwords, smem);
        return;
    }
    while (true) {
        if (tid == 0) s_job = atomicAdd(&g_ctrl[2305], 1);
        __syncthreads();
        int job = s_job;
        if (job >= NJOBS) break;
        gemm_role(job >> 6, job & 63, x, W, bias, smem);
        __syncthreads();
    }
}

// ---------------- launch ----------------
extern "C" void kernel_launch(void* const* d_in, const int* in_sizes, int n_in,
                              void* d_out, int out_size) {
    const float* x = (const float*)d_in[0];
    const int* nwords = (const int*)d_in[1];
    const float* W = (const float*)d_in[2];
    const float* trans = (const float*)d_in[3];
    const float* bias = (const float*)d_in[4];
    float* out = (float*)d_out;

    const int BT = Bn * Tn;
    int write_pred = 1, write_score = 0;
    long long score_off = BT;
    if (out_size >= BT + Bn) {
        write_score = 1;
    } else if (out_size == Bn) {
        write_pred = 0;
        write_score = 1;
        score_off = 0;
    }

    static int* ctrl_ptr = nullptr;
    if (!ctrl_ptr) cudaGetSymbolAddress((void**)&ctrl_ptr, g_ctrl);

    cudaFuncSetAttribute(crf_fused, cudaFuncAttributeMaxDynamicSharedMemorySize, SMEM_BYTES);

    cudaMemsetAsync(ctrl_ptr, 0, (2048 + 256 + 2) * sizeof(int));
    crf_fused<<<NBLOCKS, 128, SMEM_BYTES>>>(x, nwords, W, trans, bias, out,
                                            write_pred, write_score, score_off);
}